// round 2
// baseline (speedup 1.0000x reference)
#include <cuda_runtime.h>
#include <math.h>

#define DMODEL 1024
#define IMGM   512
#define NHEADS 16
#define DK     64
#define BATCH  8
#define LQ_    2048
#define LKV_   1024

// Scratch (static device globals -- no allocations allowed)
__device__ float g_Qp[(size_t)BATCH * LQ_ * DMODEL];    // 64 MB
__device__ float g_Kp[(size_t)BATCH * LKV_ * DMODEL];   // 32 MB
__device__ float g_Vp[(size_t)BATCH * LKV_ * DMODEL];   // 32 MB
__device__ float g_Ctx[(size_t)BATCH * LQ_ * DMODEL];   // 64 MB

// ---------------------------------------------------------------------------
// Tiled SGEMM: C[M,N] = A[M,K] @ W[K,N] + bias[N]
// 128x128 block tile, BK=8, 256 threads, 8x8 per-thread microtile split into
// 4+4 row/col chunks at offsets {0, 64} for conflict-free float4 smem reads.
// Requires M%128==0, N%128==0, K%8==0 (true for all shapes here).
// ---------------------------------------------------------------------------
__global__ void __launch_bounds__(256) gemm_bias_kernel(
    const float* __restrict__ A, const float* __restrict__ W,
    const float* __restrict__ bias, float* __restrict__ C,
    int M, int N, int K)
{
    __shared__ float As[8][128];
    __shared__ float Bs[8][128];

    const int tid = threadIdx.x;
    const int bm = blockIdx.y * 128;
    const int bn = blockIdx.x * 128;
    const int tx = tid & 15;       // 0..15 -> col groups
    const int ty = tid >> 4;       // 0..15 -> row groups

    // A tile loader: 128 rows x 8 cols; each thread: one float4 along K
    const int a_row = tid >> 1;           // 0..127
    const int a_col = (tid & 1) * 4;      // 0 or 4
    // B tile loader: 8 rows x 128 cols; each thread: one float4 along N
    const int b_row = tid >> 5;           // 0..7
    const int b_col = (tid & 31) * 4;     // 0..124

    const float* Aptr = A + (size_t)(bm + a_row) * K + a_col;
    const float* Wptr = W + (size_t)b_row * N + bn + b_col;

    float acc[8][8];
    #pragma unroll
    for (int i = 0; i < 8; i++)
        #pragma unroll
        for (int j = 0; j < 8; j++) acc[i][j] = 0.f;

    for (int k0 = 0; k0 < K; k0 += 8) {
        float4 av = *reinterpret_cast<const float4*>(Aptr + k0);
        float4 bv = *reinterpret_cast<const float4*>(Wptr + (size_t)k0 * N);
        As[a_col + 0][a_row] = av.x;
        As[a_col + 1][a_row] = av.y;
        As[a_col + 2][a_row] = av.z;
        As[a_col + 3][a_row] = av.w;
        *reinterpret_cast<float4*>(&Bs[b_row][b_col]) = bv;
        __syncthreads();

        #pragma unroll
        for (int kk = 0; kk < 8; kk++) {
            float4 a0 = *reinterpret_cast<const float4*>(&As[kk][ty * 4]);
            float4 a1 = *reinterpret_cast<const float4*>(&As[kk][64 + ty * 4]);
            float4 b0 = *reinterpret_cast<const float4*>(&Bs[kk][tx * 4]);
            float4 b1 = *reinterpret_cast<const float4*>(&Bs[kk][64 + tx * 4]);
            float ar[8] = {a0.x, a0.y, a0.z, a0.w, a1.x, a1.y, a1.z, a1.w};
            float br[8] = {b0.x, b0.y, b0.z, b0.w, b1.x, b1.y, b1.z, b1.w};
            #pragma unroll
            for (int i = 0; i < 8; i++)
                #pragma unroll
                for (int j = 0; j < 8; j++)
                    acc[i][j] += ar[i] * br[j];
        }
        __syncthreads();
    }

    #pragma unroll
    for (int i = 0; i < 8; i++) {
        int row = bm + ((i < 4) ? (ty * 4 + i) : (64 + ty * 4 + (i - 4)));
        #pragma unroll
        for (int jc = 0; jc < 2; jc++) {
            int col = bn + jc * 64 + tx * 4;
            float4 r;
            r.x = acc[i][jc * 4 + 0] + bias[col + 0];
            r.y = acc[i][jc * 4 + 1] + bias[col + 1];
            r.z = acc[i][jc * 4 + 2] + bias[col + 2];
            r.w = acc[i][jc * 4 + 3] + bias[col + 3];
            *reinterpret_cast<float4*>(&C[(size_t)row * N + col]) = r;
        }
    }
}

// ---------------------------------------------------------------------------
// Fused attention (flash-style, online softmax).
// One block = 64 queries of one (b, h). KV processed in tiles of 128.
// 256 threads = 8 warps; warp w owns queries w*8 .. w*8+7.
// Per lane: 8 query accumulators over d = {lane, lane+32}.
// Smem rows padded to 65 floats for conflict-free strided access.
// ---------------------------------------------------------------------------
#define ATTN_SMEM_FLOATS (64 * 65 + 128 * 65 + 128 * 65 + 64 * 128)

__global__ void __launch_bounds__(256) attn_kernel(
    const float* __restrict__ Qp, const float* __restrict__ Kp,
    const float* __restrict__ Vp, float* __restrict__ Ctx)
{
    extern __shared__ float sm[];
    float (*Qs)[65]  = reinterpret_cast<float(*)[65]>(sm);
    float (*Ks)[65]  = reinterpret_cast<float(*)[65]>(sm + 64 * 65);
    float (*Vs)[65]  = reinterpret_cast<float(*)[65]>(sm + 64 * 65 + 128 * 65);
    float (*Ss)[128] = reinterpret_cast<float(*)[128]>(sm + 64 * 65 + 2 * 128 * 65);

    const int qt = blockIdx.x;   // query tile 0..31
    const int h  = blockIdx.y;   // head
    const int b  = blockIdx.z;   // batch
    const int tid  = threadIdx.x;
    const int lane = tid & 31;
    const int warp = tid >> 5;
    const float scale = 0.125f;  // 1/sqrt(64)

    // Load Q tile: 64 rows x 64 cols (head slice)
    const float* Qbase = Qp + ((size_t)b * LQ_ + (size_t)qt * 64) * DMODEL + h * DK;
    for (int i = tid; i < 64 * 16; i += 256) {
        int r = i >> 4, c4 = (i & 15) * 4;
        float4 qv = *reinterpret_cast<const float4*>(Qbase + (size_t)r * DMODEL + c4);
        Qs[r][c4 + 0] = qv.x; Qs[r][c4 + 1] = qv.y;
        Qs[r][c4 + 2] = qv.z; Qs[r][c4 + 3] = qv.w;
    }

    float mrow[8], lrow[8], o0[8], o1[8];
    #pragma unroll
    for (int q = 0; q < 8; q++) {
        mrow[q] = -1e30f; lrow[q] = 0.f; o0[q] = 0.f; o1[q] = 0.f;
    }

    const float* Kbase = Kp + (size_t)b * LKV_ * DMODEL + h * DK;
    const float* Vbase = Vp + (size_t)b * LKV_ * DMODEL + h * DK;

    for (int kv0 = 0; kv0 < LKV_; kv0 += 128) {
        __syncthreads();  // previous tile fully consumed
        for (int i = tid; i < 128 * 16; i += 256) {
            int r = i >> 4, c4 = (i & 15) * 4;
            const float* kp = Kbase + (size_t)(kv0 + r) * DMODEL + c4;
            const float* vp = Vbase + (size_t)(kv0 + r) * DMODEL + c4;
            float4 kvv = *reinterpret_cast<const float4*>(kp);
            float4 vvv = *reinterpret_cast<const float4*>(vp);
            Ks[r][c4 + 0] = kvv.x; Ks[r][c4 + 1] = kvv.y;
            Ks[r][c4 + 2] = kvv.z; Ks[r][c4 + 3] = kvv.w;
            Vs[r][c4 + 0] = vvv.x; Vs[r][c4 + 1] = vvv.y;
            Vs[r][c4 + 2] = vvv.z; Vs[r][c4 + 3] = vvv.w;
        }
        __syncthreads();

        // ---- QK^T: lane computes s for j = lane + {0,32,64,96}, 8 queries ----
        float s[8][4];
        #pragma unroll
        for (int q = 0; q < 8; q++)
            #pragma unroll
            for (int jj = 0; jj < 4; jj++) s[q][jj] = 0.f;

        #pragma unroll 4
        for (int d = 0; d < 64; d++) {
            float k0 = Ks[lane      ][d];
            float k1 = Ks[lane + 32 ][d];
            float k2 = Ks[lane + 64 ][d];
            float k3 = Ks[lane + 96 ][d];
            #pragma unroll
            for (int q = 0; q < 8; q++) {
                float a = Qs[warp * 8 + q][d];
                s[q][0] += a * k0;
                s[q][1] += a * k1;
                s[q][2] += a * k2;
                s[q][3] += a * k3;
            }
        }

        // ---- online softmax per query ----
        #pragma unroll
        for (int q = 0; q < 8; q++) {
            int qi = warp * 8 + q;
            float s0 = s[q][0] * scale, s1 = s[q][1] * scale;
            float s2 = s[q][2] * scale, s3 = s[q][3] * scale;
            float tmax = fmaxf(fmaxf(s0, s1), fmaxf(s2, s3));
            #pragma unroll
            for (int off = 16; off > 0; off >>= 1)
                tmax = fmaxf(tmax, __shfl_xor_sync(0xFFFFFFFFu, tmax, off));
            float newm = fmaxf(mrow[q], tmax);
            float corr = __expf(mrow[q] - newm);
            float p0 = __expf(s0 - newm);
            float p1 = __expf(s1 - newm);
            float p2 = __expf(s2 - newm);
            float p3 = __expf(s3 - newm);
            Ss[qi][lane      ] = p0;
            Ss[qi][lane + 32 ] = p1;
            Ss[qi][lane + 64 ] = p2;
            Ss[qi][lane + 96 ] = p3;
            float psum = p0 + p1 + p2 + p3;
            #pragma unroll
            for (int off = 16; off > 0; off >>= 1)
                psum += __shfl_xor_sync(0xFFFFFFFFu, psum, off);
            lrow[q] = lrow[q] * corr + psum;
            mrow[q] = newm;
            o0[q] *= corr;
            o1[q] *= corr;
        }
        __syncwarp();

        // ---- PV: accumulate per-lane d-columns {lane, lane+32} ----
        #pragma unroll 4
        for (int j = 0; j < 128; j++) {
            float v0 = Vs[j][lane];
            float v1 = Vs[j][lane + 32];
            #pragma unroll
            for (int q = 0; q < 8; q++) {
                float p = Ss[warp * 8 + q][j];
                o0[q] += p * v0;
                o1[q] += p * v1;
            }
        }
        __syncwarp();
    }

    // epilogue
    #pragma unroll
    for (int q = 0; q < 8; q++) {
        int qi = warp * 8 + q;
        float inv = 1.f / lrow[q];
        size_t base = ((size_t)b * LQ_ + (size_t)qt * 64 + qi) * DMODEL + h * DK;
        Ctx[base + lane]      = o0[q] * inv;
        Ctx[base + 32 + lane] = o1[q] * inv;
    }
}

// ---------------------------------------------------------------------------
extern "C" void kernel_launch(void* const* d_in, const int* in_sizes, int n_in,
                              void* d_out, int out_size)
{
    const float* q  = (const float*)d_in[0];
    const float* k  = (const float*)d_in[1];
    const float* v  = (const float*)d_in[2];
    const float* Wq = (const float*)d_in[3];
    const float* bq = (const float*)d_in[4];
    const float* Wk = (const float*)d_in[5];
    const float* bk = (const float*)d_in[6];
    const float* Wv = (const float*)d_in[7];
    const float* bv = (const float*)d_in[8];
    const float* Wo = (const float*)d_in[9];
    const float* bo = (const float*)d_in[10];
    float* out = (float*)d_out;

    float *Qp, *Kp, *Vp, *Ctx;
    cudaGetSymbolAddress((void**)&Qp, g_Qp);
    cudaGetSymbolAddress((void**)&Kp, g_Kp);
    cudaGetSymbolAddress((void**)&Vp, g_Vp);
    cudaGetSymbolAddress((void**)&Ctx, g_Ctx);

    const int smem_attn = ATTN_SMEM_FLOATS * (int)sizeof(float);
    cudaFuncSetAttribute(attn_kernel, cudaFuncAttributeMaxDynamicSharedMemorySize,
                         smem_attn);

    // Q projection: [16384,1024] @ [1024,1024]
    gemm_bias_kernel<<<dim3(DMODEL / 128, (BATCH * LQ_) / 128), 256>>>(
        q, Wq, bq, Qp, BATCH * LQ_, DMODEL, DMODEL);
    // K projection: [8192,512] @ [512,1024]
    gemm_bias_kernel<<<dim3(DMODEL / 128, (BATCH * LKV_) / 128), 256>>>(
        k, Wk, bk, Kp, BATCH * LKV_, DMODEL, IMGM);
    // V projection
    gemm_bias_kernel<<<dim3(DMODEL / 128, (BATCH * LKV_) / 128), 256>>>(
        v, Wv, bv, Vp, BATCH * LKV_, DMODEL, IMGM);

    // Fused attention -> Ctx
    attn_kernel<<<dim3(LQ_ / 64, NHEADS, BATCH), 256, smem_attn>>>(Qp, Kp, Vp, Ctx);

    // Output projection: [16384,1024] @ [1024,1024] -> out
    gemm_bias_kernel<<<dim3(DMODEL / 128, (BATCH * LQ_) / 128), 256>>>(
        Ctx, Wo, bo, out, BATCH * LQ_, DMODEL, DMODEL);
}

// round 4
// speedup vs baseline: 1.2584x; 1.2584x over previous
#include <cuda_runtime.h>
#include <cuda_bf16.h>
#include <cstdint>
#include <math.h>

#define DMODEL 1024
#define IMGM   512
#define NHEADS 16
#define DK     64
#define BATCH  8
#define LQ_    2048
#define LKV_   1024
#define MQ   (BATCH * LQ_)    // 16384
#define MKV  (BATCH * LKV_)   // 8192

// ---------------- scratch (static device globals; no allocs allowed) -------
__device__ float g_Qp [(size_t)MQ  * DMODEL];
__device__ float g_Kp [(size_t)MKV * DMODEL];
__device__ float g_Vp [(size_t)MKV * DMODEL];
__device__ float g_Ctx[(size_t)MQ  * DMODEL];

__device__ __nv_bfloat16 g_q_hi[(size_t)MQ  * DMODEL], g_q_lo[(size_t)MQ  * DMODEL];
__device__ __nv_bfloat16 g_k_hi[(size_t)MKV * IMGM ], g_k_lo[(size_t)MKV * IMGM ];
__device__ __nv_bfloat16 g_v_hi[(size_t)MKV * IMGM ], g_v_lo[(size_t)MKV * IMGM ];
__device__ __nv_bfloat16 g_c_hi[(size_t)MQ  * DMODEL], g_c_lo[(size_t)MQ  * DMODEL];

// transposed weights: Wt[N][K] = W[K][N]  (k-contiguous => mma.sync ".col" B)
__device__ __nv_bfloat16 g_Wqt_hi[DMODEL * DMODEL], g_Wqt_lo[DMODEL * DMODEL];
__device__ __nv_bfloat16 g_Wkt_hi[DMODEL * IMGM ], g_Wkt_lo[DMODEL * IMGM ];
__device__ __nv_bfloat16 g_Wvt_hi[DMODEL * IMGM ], g_Wvt_lo[DMODEL * IMGM ];
__device__ __nv_bfloat16 g_Wot_hi[DMODEL * DMODEL], g_Wot_lo[DMODEL * DMODEL];

// ---------------- PTX helpers ----------------------------------------------
__device__ __forceinline__ uint32_t smem_u32(const void* p) {
    uint32_t a;
    asm("{ .reg .u64 t; cvta.to.shared.u64 t, %1; cvt.u32.u64 %0, t; }"
        : "=r"(a) : "l"(p));
    return a;
}
__device__ __forceinline__ void ldsm_x4(uint32_t* r, uint32_t addr) {
    asm volatile("ldmatrix.sync.aligned.m8n8.x4.shared.b16 {%0,%1,%2,%3}, [%4];"
                 : "=r"(r[0]), "=r"(r[1]), "=r"(r[2]), "=r"(r[3]) : "r"(addr));
}
__device__ __forceinline__ void ldsm_x2(uint32_t* r, uint32_t addr) {
    asm volatile("ldmatrix.sync.aligned.m8n8.x2.shared.b16 {%0,%1}, [%2];"
                 : "=r"(r[0]), "=r"(r[1]) : "r"(addr));
}
__device__ __forceinline__ void mma_bf16(float* c, const uint32_t* a, const uint32_t* b) {
    asm volatile(
        "mma.sync.aligned.m16n8k16.row.col.f32.bf16.bf16.f32 "
        "{%0,%1,%2,%3}, {%4,%5,%6,%7}, {%8,%9}, {%0,%1,%2,%3};"
        : "+f"(c[0]), "+f"(c[1]), "+f"(c[2]), "+f"(c[3])
        : "r"(a[0]), "r"(a[1]), "r"(a[2]), "r"(a[3]), "r"(b[0]), "r"(b[1]));
}
#define CP_ASYNC16(dst, src) \
    asm volatile("cp.async.cg.shared.global [%0], [%1], 16;" :: "r"(dst), "l"(src) : "memory")
#define CP_COMMIT()  asm volatile("cp.async.commit_group;" ::: "memory")
#define CP_WAIT(n)   asm volatile("cp.async.wait_group %0;" :: "n"(n) : "memory")

// ---------------------------------------------------------------------------
// HMMA bf16 GEMM with 3-term hi/lo split:
//   C[M,N] = Ah@Bh^T + Ah@Bl^T + Al@Bh^T + bias   (B stored as Bt[N][K])
// Block 128x128, BK=32. 8 warps: 2(M) x 4(N), warp tile 64x32.
// Smem tiles: rows padded to 40 bf16 (80B) -> conflict-free ldmatrix.
// ---------------------------------------------------------------------------
#define GT_PAD_K      40
#define GT_TILE_B     (128 * GT_PAD_K * 2)        // 10240 bytes
#define GT_STAGE_B    (4 * GT_TILE_B)             // 40960
#define GT_SMEM_TOTAL (2 * GT_STAGE_B)            // 81920

__device__ __forceinline__ void gt_load_stage(
    uint32_t stage, const __nv_bfloat16* __restrict__ Ah,
    const __nv_bfloat16* __restrict__ Al, const __nv_bfloat16* __restrict__ Bh,
    const __nv_bfloat16* __restrict__ Bl,
    int bm, int bn, int K, int k0, int tid)
{
    const __nv_bfloat16* srcs[4];
    srcs[0] = Ah + (size_t)bm * K + k0;
    srcs[1] = Al + (size_t)bm * K + k0;
    srcs[2] = Bh + (size_t)bn * K + k0;
    srcs[3] = Bl + (size_t)bn * K + k0;
    #pragma unroll
    for (int i = 0; i < 8; i++) {
        int cid  = i * 256 + tid;        // 0..2047
        int tile = cid >> 9;             // 0..3
        int c    = cid & 511;
        int row  = c >> 2;               // 0..127
        int ch   = c & 3;                // 16B chunk in row
        uint32_t dst = stage + tile * GT_TILE_B + (uint32_t)(row * GT_PAD_K + ch * 8) * 2;
        const __nv_bfloat16* src = srcs[tile] + (size_t)row * K + ch * 8;
        CP_ASYNC16(dst, src);
    }
}

__global__ void __launch_bounds__(256) gemm_tc_kernel(
    const __nv_bfloat16* __restrict__ Ah, const __nv_bfloat16* __restrict__ Al,
    const __nv_bfloat16* __restrict__ Bh, const __nv_bfloat16* __restrict__ Bl,
    const float* __restrict__ bias, float* __restrict__ C,
    int M, int N, int K)
{
    extern __shared__ char smem[];
    const uint32_t sb = smem_u32(smem);
    const int tid  = threadIdx.x;
    const int lane = tid & 31;
    const int wid  = tid >> 5;
    const int wm   = wid & 1;            // 0..1 (M)
    const int wn   = wid >> 1;           // 0..3 (N)
    const int bn   = blockIdx.x * 128;
    const int bm   = blockIdx.y * 128;

    float acc[4][4][4];
    #pragma unroll
    for (int mt = 0; mt < 4; mt++)
        #pragma unroll
        for (int nt = 0; nt < 4; nt++)
            #pragma unroll
            for (int j = 0; j < 4; j++) acc[mt][nt][j] = 0.f;

    const int KT = K >> 5;

    gt_load_stage(sb, Ah, Al, Bh, Bl, bm, bn, K, 0, tid);
    CP_COMMIT();

    // ldmatrix lane address components
    const int a_r = lane & 15;           // row within 16
    const int a_c = (lane >> 4) * 8;     // k-half
    const int b_r = lane & 7;
    const int b_c = ((lane >> 3) & 1) * 8;

    for (int s = 0; s < KT; s++) {
        if (s + 1 < KT) {
            gt_load_stage(sb + ((s + 1) & 1) * GT_STAGE_B, Ah, Al, Bh, Bl,
                          bm, bn, K, (s + 1) * 32, tid);
            CP_COMMIT();
            CP_WAIT(1);
        } else {
            CP_WAIT(0);
        }
        __syncthreads();

        const uint32_t st  = sb + (s & 1) * GT_STAGE_B;
        const uint32_t sAh = st + 0 * GT_TILE_B;
        const uint32_t sAl = st + 1 * GT_TILE_B;
        const uint32_t sBh = st + 2 * GT_TILE_B;
        const uint32_t sBl = st + 3 * GT_TILE_B;

        #pragma unroll
        for (int kk = 0; kk < 32; kk += 16) {
            uint32_t ah[4][4], al[4][4], bh[4][2], bl[4][2];
            #pragma unroll
            for (int mt = 0; mt < 4; mt++) {
                int row = wm * 64 + mt * 16 + a_r;
                uint32_t off = (uint32_t)(row * GT_PAD_K + kk + a_c) * 2;
                ldsm_x4(ah[mt], sAh + off);
                ldsm_x4(al[mt], sAl + off);
            }
            #pragma unroll
            for (int nt = 0; nt < 4; nt++) {
                int row = wn * 32 + nt * 8 + b_r;
                uint32_t off = (uint32_t)(row * GT_PAD_K + kk + b_c) * 2;
                ldsm_x2(bh[nt], sBh + off);
                ldsm_x2(bl[nt], sBl + off);
            }
            #pragma unroll
            for (int mt = 0; mt < 4; mt++)
                #pragma unroll
                for (int nt = 0; nt < 4; nt++) {
                    mma_bf16(acc[mt][nt], ah[mt], bh[nt]);
                    mma_bf16(acc[mt][nt], ah[mt], bl[nt]);
                    mma_bf16(acc[mt][nt], al[mt], bh[nt]);
                }
        }
        __syncthreads();
    }

    // epilogue: fragment layout m16n8 -> (row t/4 [+8], col 2*(t%4) [+1])
    const int er = lane >> 2;
    const int ec = (lane & 3) * 2;
    #pragma unroll
    for (int mt = 0; mt < 4; mt++) {
        #pragma unroll
        for (int nt = 0; nt < 4; nt++) {
            int row0 = bm + wm * 64 + mt * 16 + er;
            int col  = bn + wn * 32 + nt * 8 + ec;
            float2 v0, v1;
            v0.x = acc[mt][nt][0] + bias[col];
            v0.y = acc[mt][nt][1] + bias[col + 1];
            v1.x = acc[mt][nt][2] + bias[col];
            v1.y = acc[mt][nt][3] + bias[col + 1];
            *reinterpret_cast<float2*>(C + (size_t)row0 * N + col)       = v0;
            *reinterpret_cast<float2*>(C + (size_t)(row0 + 8) * N + col) = v1;
        }
    }
}

// ---------------------------------------------------------------------------
// fp32 -> bf16 hi/lo split (elementwise, vectorized x4)
// ---------------------------------------------------------------------------
__global__ void __launch_bounds__(256) split_kernel(
    const float* __restrict__ x, __nv_bfloat16* __restrict__ hi,
    __nv_bfloat16* __restrict__ lo, int n4)
{
    int i = blockIdx.x * 256 + threadIdx.x;
    if (i >= n4) return;
    float4 v = reinterpret_cast<const float4*>(x)[i];
    float h0 = __bfloat162float(__float2bfloat16_rn(v.x));
    float h1 = __bfloat162float(__float2bfloat16_rn(v.y));
    float h2 = __bfloat162float(__float2bfloat16_rn(v.z));
    float h3 = __bfloat162float(__float2bfloat16_rn(v.w));
    __nv_bfloat162 hp0, hp1, lp0, lp1;
    hp0.x = __float2bfloat16_rn(v.x); hp0.y = __float2bfloat16_rn(v.y);
    hp1.x = __float2bfloat16_rn(v.z); hp1.y = __float2bfloat16_rn(v.w);
    lp0.x = __float2bfloat16_rn(v.x - h0); lp0.y = __float2bfloat16_rn(v.y - h1);
    lp1.x = __float2bfloat16_rn(v.z - h2); lp1.y = __float2bfloat16_rn(v.w - h3);
    reinterpret_cast<__nv_bfloat162*>(hi)[i * 2 + 0] = hp0;
    reinterpret_cast<__nv_bfloat162*>(hi)[i * 2 + 1] = hp1;
    reinterpret_cast<__nv_bfloat162*>(lo)[i * 2 + 0] = lp0;
    reinterpret_cast<__nv_bfloat162*>(lo)[i * 2 + 1] = lp1;
}

// W[K,N] -> Wt_hi/lo[N][K]  (transpose + split)
__global__ void __launch_bounds__(256) split_transpose_kernel(
    const float* __restrict__ W, __nv_bfloat16* __restrict__ Th,
    __nv_bfloat16* __restrict__ Tl, int K, int N)
{
    __shared__ float t[32][33];
    const int n0 = blockIdx.x * 32, k0 = blockIdx.y * 32;
    const int tx = threadIdx.x, ty = threadIdx.y;  // 32 x 8
    #pragma unroll
    for (int i = ty; i < 32; i += 8)
        t[i][tx] = W[(size_t)(k0 + i) * N + n0 + tx];
    __syncthreads();
    #pragma unroll
    for (int i = ty; i < 32; i += 8) {
        float x = t[tx][i];                       // = W[k0+tx][n0+i]
        __nv_bfloat16 h = __float2bfloat16_rn(x);
        float hf = __bfloat162float(h);
        Th[(size_t)(n0 + i) * K + k0 + tx] = h;
        Tl[(size_t)(n0 + i) * K + k0 + tx] = __float2bfloat16_rn(x - hf);
    }
}

// ---------------------------------------------------------------------------
// Fused attention (flash-style, fp32 SIMT)
// ---------------------------------------------------------------------------
#define ATTN_SMEM_FLOATS (64 * 65 + 128 * 65 + 128 * 65 + 64 * 128)

__global__ void __launch_bounds__(256) attn_kernel(
    const float* __restrict__ Qp, const float* __restrict__ Kp,
    const float* __restrict__ Vp, float* __restrict__ Ctx)
{
    extern __shared__ float sm[];
    float (*Qs)[65]  = reinterpret_cast<float(*)[65]>(sm);
    float (*Ks)[65]  = reinterpret_cast<float(*)[65]>(sm + 64 * 65);
    float (*Vs)[65]  = reinterpret_cast<float(*)[65]>(sm + 64 * 65 + 128 * 65);
    float (*Ss)[128] = reinterpret_cast<float(*)[128]>(sm + 64 * 65 + 2 * 128 * 65);

    const int qt = blockIdx.x, h = blockIdx.y, b = blockIdx.z;
    const int tid = threadIdx.x, lane = tid & 31, warp = tid >> 5;
    const float scale = 0.125f;

    const float* Qbase = Qp + ((size_t)b * LQ_ + (size_t)qt * 64) * DMODEL + h * DK;
    for (int i = tid; i < 64 * 16; i += 256) {
        int r = i >> 4, c4 = (i & 15) * 4;
        float4 qv = *reinterpret_cast<const float4*>(Qbase + (size_t)r * DMODEL + c4);
        Qs[r][c4 + 0] = qv.x; Qs[r][c4 + 1] = qv.y;
        Qs[r][c4 + 2] = qv.z; Qs[r][c4 + 3] = qv.w;
    }

    float mrow[8], lrow[8], o0[8], o1[8];
    #pragma unroll
    for (int q = 0; q < 8; q++) { mrow[q] = -1e30f; lrow[q] = 0.f; o0[q] = 0.f; o1[q] = 0.f; }

    const float* Kbase = Kp + (size_t)b * LKV_ * DMODEL + h * DK;
    const float* Vbase = Vp + (size_t)b * LKV_ * DMODEL + h * DK;

    for (int kv0 = 0; kv0 < LKV_; kv0 += 128) {
        __syncthreads();
        for (int i = tid; i < 128 * 16; i += 256) {
            int r = i >> 4, c4 = (i & 15) * 4;
            const float* kp = Kbase + (size_t)(kv0 + r) * DMODEL + c4;
            const float* vp = Vbase + (size_t)(kv0 + r) * DMODEL + c4;
            float4 kvv = *reinterpret_cast<const float4*>(kp);
            float4 vvv = *reinterpret_cast<const float4*>(vp);
            Ks[r][c4 + 0] = kvv.x; Ks[r][c4 + 1] = kvv.y;
            Ks[r][c4 + 2] = kvv.z; Ks[r][c4 + 3] = kvv.w;
            Vs[r][c4 + 0] = vvv.x; Vs[r][c4 + 1] = vvv.y;
            Vs[r][c4 + 2] = vvv.z; Vs[r][c4 + 3] = vvv.w;
        }
        __syncthreads();

        float s[8][4];
        #pragma unroll
        for (int q = 0; q < 8; q++)
            #pragma unroll
            for (int jj = 0; jj < 4; jj++) s[q][jj] = 0.f;

        #pragma unroll 4
        for (int d = 0; d < 64; d++) {
            float k0 = Ks[lane      ][d];
            float k1 = Ks[lane + 32 ][d];
            float k2 = Ks[lane + 64 ][d];
            float k3 = Ks[lane + 96 ][d];
            #pragma unroll
            for (int q = 0; q < 8; q++) {
                float a = Qs[warp * 8 + q][d];
                s[q][0] += a * k0; s[q][1] += a * k1;
                s[q][2] += a * k2; s[q][3] += a * k3;
            }
        }

        #pragma unroll
        for (int q = 0; q < 8; q++) {
            int qi = warp * 8 + q;
            float s0 = s[q][0] * scale, s1 = s[q][1] * scale;
            float s2 = s[q][2] * scale, s3 = s[q][3] * scale;
            float tmax = fmaxf(fmaxf(s0, s1), fmaxf(s2, s3));
            #pragma unroll
            for (int off = 16; off > 0; off >>= 1)
                tmax = fmaxf(tmax, __shfl_xor_sync(0xFFFFFFFFu, tmax, off));
            float newm = fmaxf(mrow[q], tmax);
            float corr = __expf(mrow[q] - newm);
            float p0 = __expf(s0 - newm), p1 = __expf(s1 - newm);
            float p2 = __expf(s2 - newm), p3 = __expf(s3 - newm);
            Ss[qi][lane      ] = p0; Ss[qi][lane + 32 ] = p1;
            Ss[qi][lane + 64 ] = p2; Ss[qi][lane + 96 ] = p3;
            float psum = p0 + p1 + p2 + p3;
            #pragma unroll
            for (int off = 16; off > 0; off >>= 1)
                psum += __shfl_xor_sync(0xFFFFFFFFu, psum, off);
            lrow[q] = lrow[q] * corr + psum;
            mrow[q] = newm;
            o0[q] *= corr; o1[q] *= corr;
        }
        __syncwarp();

        #pragma unroll 4
        for (int j = 0; j < 128; j++) {
            float v0 = Vs[j][lane];
            float v1 = Vs[j][lane + 32];
            #pragma unroll
            for (int q = 0; q < 8; q++) {
                float p = Ss[warp * 8 + q][j];
                o0[q] += p * v0; o1[q] += p * v1;
            }
        }
        __syncwarp();
    }

    #pragma unroll
    for (int q = 0; q < 8; q++) {
        int qi = warp * 8 + q;
        float inv = 1.f / lrow[q];
        size_t base = ((size_t)b * LQ_ + (size_t)qt * 64 + qi) * DMODEL + h * DK;
        Ctx[base + lane]      = o0[q] * inv;
        Ctx[base + 32 + lane] = o1[q] * inv;
    }
}

// ---------------------------------------------------------------------------
extern "C" void kernel_launch(void* const* d_in, const int* in_sizes, int n_in,
                              void* d_out, int out_size)
{
    const float* q  = (const float*)d_in[0];
    const float* k  = (const float*)d_in[1];
    const float* v  = (const float*)d_in[2];
    const float* Wq = (const float*)d_in[3];
    const float* bq = (const float*)d_in[4];
    const float* Wk = (const float*)d_in[5];
    const float* bk = (const float*)d_in[6];
    const float* Wv = (const float*)d_in[7];
    const float* bv = (const float*)d_in[8];
    const float* Wo = (const float*)d_in[9];
    const float* bo = (const float*)d_in[10];
    float* out = (float*)d_out;

    float *Qp, *Kp, *Vp, *Ctx;
    cudaGetSymbolAddress((void**)&Qp,  g_Qp);
    cudaGetSymbolAddress((void**)&Kp,  g_Kp);
    cudaGetSymbolAddress((void**)&Vp,  g_Vp);
    cudaGetSymbolAddress((void**)&Ctx, g_Ctx);

    __nv_bfloat16 *qh, *ql, *kh, *kl, *vh, *vl, *ch, *cl;
    __nv_bfloat16 *Wqh, *Wql, *Wkh, *Wkl, *Wvh, *Wvl, *Woh, *Wol;
    cudaGetSymbolAddress((void**)&qh, g_q_hi);  cudaGetSymbolAddress((void**)&ql, g_q_lo);
    cudaGetSymbolAddress((void**)&kh, g_k_hi);  cudaGetSymbolAddress((void**)&kl, g_k_lo);
    cudaGetSymbolAddress((void**)&vh, g_v_hi);  cudaGetSymbolAddress((void**)&vl, g_v_lo);
    cudaGetSymbolAddress((void**)&ch, g_c_hi);  cudaGetSymbolAddress((void**)&cl, g_c_lo);
    cudaGetSymbolAddress((void**)&Wqh, g_Wqt_hi); cudaGetSymbolAddress((void**)&Wql, g_Wqt_lo);
    cudaGetSymbolAddress((void**)&Wkh, g_Wkt_hi); cudaGetSymbolAddress((void**)&Wkl, g_Wkt_lo);
    cudaGetSymbolAddress((void**)&Wvh, g_Wvt_hi); cudaGetSymbolAddress((void**)&Wvl, g_Wvt_lo);
    cudaGetSymbolAddress((void**)&Woh, g_Wot_hi); cudaGetSymbolAddress((void**)&Wol, g_Wot_lo);

    cudaFuncSetAttribute(gemm_tc_kernel,
                         cudaFuncAttributeMaxDynamicSharedMemorySize, GT_SMEM_TOTAL);
    const int smem_attn = ATTN_SMEM_FLOATS * (int)sizeof(float);
    cudaFuncSetAttribute(attn_kernel,
                         cudaFuncAttributeMaxDynamicSharedMemorySize, smem_attn);

    // ---- split activations + weights to bf16 hi/lo ----
    {
        int n4;
        n4 = MQ * DMODEL / 4;  split_kernel<<<(n4 + 255) / 256, 256>>>(q, qh, ql, n4);
        n4 = MKV * IMGM / 4;   split_kernel<<<(n4 + 255) / 256, 256>>>(k, kh, kl, n4);
        n4 = MKV * IMGM / 4;   split_kernel<<<(n4 + 255) / 256, 256>>>(v, vh, vl, n4);
        dim3 tb(32, 8);
        split_transpose_kernel<<<dim3(DMODEL / 32, DMODEL / 32), tb>>>(Wq, Wqh, Wql, DMODEL, DMODEL);
        split_transpose_kernel<<<dim3(DMODEL / 32, IMGM  / 32), tb>>>(Wk, Wkh, Wkl, IMGM,  DMODEL);
        split_transpose_kernel<<<dim3(DMODEL / 32, IMGM  / 32), tb>>>(Wv, Wvh, Wvl, IMGM,  DMODEL);
        split_transpose_kernel<<<dim3(DMODEL / 32, DMODEL / 32), tb>>>(Wo, Woh, Wol, DMODEL, DMODEL);
    }

    // ---- projections (HMMA mma.sync) ----
    gemm_tc_kernel<<<dim3(DMODEL / 128, MQ / 128),  256, GT_SMEM_TOTAL>>>(
        qh, ql, Wqh, Wql, bq, Qp, MQ, DMODEL, DMODEL);
    gemm_tc_kernel<<<dim3(DMODEL / 128, MKV / 128), 256, GT_SMEM_TOTAL>>>(
        kh, kl, Wkh, Wkl, bk, Kp, MKV, DMODEL, IMGM);
    gemm_tc_kernel<<<dim3(DMODEL / 128, MKV / 128), 256, GT_SMEM_TOTAL>>>(
        vh, vl, Wvh, Wvl, bv, Vp, MKV, DMODEL, IMGM);

    // ---- fused attention (fp32) ----
    attn_kernel<<<dim3(LQ_ / 64, NHEADS, BATCH), 256, smem_attn>>>(Qp, Kp, Vp, Ctx);

    // ---- output projection ----
    {
        int n4 = MQ * DMODEL / 4;
        split_kernel<<<(n4 + 255) / 256, 256>>>(Ctx, ch, cl, n4);
    }
    gemm_tc_kernel<<<dim3(DMODEL / 128, MQ / 128), 256, GT_SMEM_TOTAL>>>(
        ch, cl, Woh, Wol, bo, out, MQ, DMODEL, DMODEL);
}

// round 6
// speedup vs baseline: 2.9673x; 2.3579x over previous
#include <cuda_runtime.h>
#include <cuda_bf16.h>
#include <cstdint>
#include <math.h>

#define DMODEL 1024
#define IMGM   512
#define NHEADS 16
#define DK     64
#define BATCH  8
#define LQ_    2048
#define LKV_   1024
#define MQ   (BATCH * LQ_)    // 16384
#define MKV  (BATCH * LKV_)   // 8192

// ---------------- scratch (static device globals; no allocs allowed) -------
// input splits
__device__ __nv_bfloat16 g_q_hi[(size_t)MQ  * DMODEL], g_q_lo[(size_t)MQ  * DMODEL];
__device__ __nv_bfloat16 g_k_hi[(size_t)MKV * IMGM ], g_k_lo[(size_t)MKV * IMGM ];
__device__ __nv_bfloat16 g_v_hi[(size_t)MKV * IMGM ], g_v_lo[(size_t)MKV * IMGM ];
// projected Q/K/V (bf16 hi/lo, written directly by GEMM epilogue)
__device__ __nv_bfloat16 g_Qph[(size_t)MQ  * DMODEL], g_Qpl[(size_t)MQ  * DMODEL];
__device__ __nv_bfloat16 g_Kph[(size_t)MKV * DMODEL], g_Kpl[(size_t)MKV * DMODEL];
__device__ __nv_bfloat16 g_Vph[(size_t)MKV * DMODEL], g_Vpl[(size_t)MKV * DMODEL];
// attention output (bf16 hi/lo, written directly by attention epilogue)
__device__ __nv_bfloat16 g_c_hi[(size_t)MQ  * DMODEL], g_c_lo[(size_t)MQ  * DMODEL];
// transposed weights: Wt[N][K] = W[K][N]  (k-contiguous => mma.sync ".col" B)
__device__ __nv_bfloat16 g_Wqt_hi[DMODEL * DMODEL], g_Wqt_lo[DMODEL * DMODEL];
__device__ __nv_bfloat16 g_Wkt_hi[DMODEL * IMGM ], g_Wkt_lo[DMODEL * IMGM ];
__device__ __nv_bfloat16 g_Wvt_hi[DMODEL * IMGM ], g_Wvt_lo[DMODEL * IMGM ];
__device__ __nv_bfloat16 g_Wot_hi[DMODEL * DMODEL], g_Wot_lo[DMODEL * DMODEL];

// ---------------- PTX helpers ----------------------------------------------
__device__ __forceinline__ uint32_t smem_u32(const void* p) {
    uint32_t a;
    asm("{ .reg .u64 t; cvta.to.shared.u64 t, %1; cvt.u32.u64 %0, t; }"
        : "=r"(a) : "l"(p));
    return a;
}
__device__ __forceinline__ void ldsm_x4(uint32_t* r, uint32_t addr) {
    asm volatile("ldmatrix.sync.aligned.m8n8.x4.shared.b16 {%0,%1,%2,%3}, [%4];"
                 : "=r"(r[0]), "=r"(r[1]), "=r"(r[2]), "=r"(r[3]) : "r"(addr));
}
__device__ __forceinline__ void ldsm_x2(uint32_t* r, uint32_t addr) {
    asm volatile("ldmatrix.sync.aligned.m8n8.x2.shared.b16 {%0,%1}, [%2];"
                 : "=r"(r[0]), "=r"(r[1]) : "r"(addr));
}
__device__ __forceinline__ void ldsm_x2_trans(uint32_t* r, uint32_t addr) {
    asm volatile("ldmatrix.sync.aligned.m8n8.x2.trans.shared.b16 {%0,%1}, [%2];"
                 : "=r"(r[0]), "=r"(r[1]) : "r"(addr));
}
__device__ __forceinline__ void mma_bf16(float* c, const uint32_t* a, const uint32_t* b) {
    asm volatile(
        "mma.sync.aligned.m16n8k16.row.col.f32.bf16.bf16.f32 "
        "{%0,%1,%2,%3}, {%4,%5,%6,%7}, {%8,%9}, {%0,%1,%2,%3};"
        : "+f"(c[0]), "+f"(c[1]), "+f"(c[2]), "+f"(c[3])
        : "r"(a[0]), "r"(a[1]), "r"(a[2]), "r"(a[3]), "r"(b[0]), "r"(b[1]));
}
#define CP_ASYNC16(dst, src) \
    asm volatile("cp.async.cg.shared.global [%0], [%1], 16;" :: "r"(dst), "l"(src) : "memory")
#define CP_COMMIT()  asm volatile("cp.async.commit_group;" ::: "memory")
#define CP_WAIT(n)   asm volatile("cp.async.wait_group %0;" :: "n"(n) : "memory")

// split x -> (bf16 hi, bf16 lo) pair packed as b32
__device__ __forceinline__ void bf16_split_pack(float a, float b,
                                                uint32_t& hi, uint32_t& lo) {
    __nv_bfloat16 ha = __float2bfloat16_rn(a), hb = __float2bfloat16_rn(b);
    float ra = a - __bfloat162float(ha);
    float rb = b - __bfloat162float(hb);
    __nv_bfloat162 hp, lp;
    hp.x = ha; hp.y = hb;
    lp.x = __float2bfloat16_rn(ra); lp.y = __float2bfloat16_rn(rb);
    hi = *reinterpret_cast<uint32_t*>(&hp);
    lo = *reinterpret_cast<uint32_t*>(&lp);
}

// ---------------------------------------------------------------------------
// HMMA bf16 GEMM, 3-term hi/lo split:
//   C = Ah@Bh^T + Ah@Bl^T + Al@Bh^T + bias   (B stored as Bt[N][K])
// Block 128x128, BK=32. 8 warps: 2(M) x 4(N), warp tile 64x32.
// Output: fp32 C, or bf16 hi/lo split (Chi/Clo) when Chi != nullptr.
// ---------------------------------------------------------------------------
#define GT_PAD_K      40
#define GT_TILE_B     (128 * GT_PAD_K * 2)        // 10240 bytes
#define GT_STAGE_B    (4 * GT_TILE_B)             // 40960
#define GT_SMEM_TOTAL (2 * GT_STAGE_B)            // 81920

__device__ __forceinline__ void gt_load_stage(
    uint32_t stage, const __nv_bfloat16* __restrict__ Ah,
    const __nv_bfloat16* __restrict__ Al, const __nv_bfloat16* __restrict__ Bh,
    const __nv_bfloat16* __restrict__ Bl,
    int bm, int bn, int K, int k0, int tid)
{
    const __nv_bfloat16* srcs[4];
    srcs[0] = Ah + (size_t)bm * K + k0;
    srcs[1] = Al + (size_t)bm * K + k0;
    srcs[2] = Bh + (size_t)bn * K + k0;
    srcs[3] = Bl + (size_t)bn * K + k0;
    #pragma unroll
    for (int i = 0; i < 8; i++) {
        int cid  = i * 256 + tid;
        int tile = cid >> 9;
        int c    = cid & 511;
        int row  = c >> 2;
        int ch   = c & 3;
        uint32_t dst = stage + tile * GT_TILE_B + (uint32_t)(row * GT_PAD_K + ch * 8) * 2;
        const __nv_bfloat16* src = srcs[tile] + (size_t)row * K + ch * 8;
        CP_ASYNC16(dst, src);
    }
}

__global__ void __launch_bounds__(256) gemm_tc_kernel(
    const __nv_bfloat16* __restrict__ Ah, const __nv_bfloat16* __restrict__ Al,
    const __nv_bfloat16* __restrict__ Bh, const __nv_bfloat16* __restrict__ Bl,
    const float* __restrict__ bias, float* __restrict__ C,
    __nv_bfloat16* __restrict__ Chi, __nv_bfloat16* __restrict__ Clo,
    int M, int N, int K)
{
    extern __shared__ char smem[];
    const uint32_t sb = smem_u32(smem);
    const int tid  = threadIdx.x;
    const int lane = tid & 31;
    const int wid  = tid >> 5;
    const int wm   = wid & 1;
    const int wn   = wid >> 1;
    const int bn   = blockIdx.x * 128;
    const int bm   = blockIdx.y * 128;

    float acc[4][4][4];
    #pragma unroll
    for (int mt = 0; mt < 4; mt++)
        #pragma unroll
        for (int nt = 0; nt < 4; nt++)
            #pragma unroll
            for (int j = 0; j < 4; j++) acc[mt][nt][j] = 0.f;

    const int KT = K >> 5;

    gt_load_stage(sb, Ah, Al, Bh, Bl, bm, bn, K, 0, tid);
    CP_COMMIT();

    const int a_r = lane & 15;
    const int a_c = (lane >> 4) * 8;
    const int b_r = lane & 7;
    const int b_c = ((lane >> 3) & 1) * 8;

    for (int s = 0; s < KT; s++) {
        if (s + 1 < KT) {
            gt_load_stage(sb + ((s + 1) & 1) * GT_STAGE_B, Ah, Al, Bh, Bl,
                          bm, bn, K, (s + 1) * 32, tid);
            CP_COMMIT();
            CP_WAIT(1);
        } else {
            CP_WAIT(0);
        }
        __syncthreads();

        const uint32_t st  = sb + (s & 1) * GT_STAGE_B;
        const uint32_t sAh = st + 0 * GT_TILE_B;
        const uint32_t sAl = st + 1 * GT_TILE_B;
        const uint32_t sBh = st + 2 * GT_TILE_B;
        const uint32_t sBl = st + 3 * GT_TILE_B;

        #pragma unroll
        for (int kk = 0; kk < 32; kk += 16) {
            uint32_t ah[4][4], al[4][4], bh[4][2], bl[4][2];
            #pragma unroll
            for (int mt = 0; mt < 4; mt++) {
                int row = wm * 64 + mt * 16 + a_r;
                uint32_t off = (uint32_t)(row * GT_PAD_K + kk + a_c) * 2;
                ldsm_x4(ah[mt], sAh + off);
                ldsm_x4(al[mt], sAl + off);
            }
            #pragma unroll
            for (int nt = 0; nt < 4; nt++) {
                int row = wn * 32 + nt * 8 + b_r;
                uint32_t off = (uint32_t)(row * GT_PAD_K + kk + b_c) * 2;
                ldsm_x2(bh[nt], sBh + off);
                ldsm_x2(bl[nt], sBl + off);
            }
            #pragma unroll
            for (int mt = 0; mt < 4; mt++)
                #pragma unroll
                for (int nt = 0; nt < 4; nt++) {
                    mma_bf16(acc[mt][nt], ah[mt], bh[nt]);
                    mma_bf16(acc[mt][nt], ah[mt], bl[nt]);
                    mma_bf16(acc[mt][nt], al[mt], bh[nt]);
                }
        }
        __syncthreads();
    }

    const int er = lane >> 2;
    const int ec = (lane & 3) * 2;
    #pragma unroll
    for (int mt = 0; mt < 4; mt++) {
        #pragma unroll
        for (int nt = 0; nt < 4; nt++) {
            int row0 = bm + wm * 64 + mt * 16 + er;
            int col  = bn + wn * 32 + nt * 8 + ec;
            float b0 = bias[col], b1 = bias[col + 1];
            float v00 = acc[mt][nt][0] + b0, v01 = acc[mt][nt][1] + b1;
            float v10 = acc[mt][nt][2] + b0, v11 = acc[mt][nt][3] + b1;
            if (Chi) {
                uint32_t h0, l0, h1, l1;
                bf16_split_pack(v00, v01, h0, l0);
                bf16_split_pack(v10, v11, h1, l1);
                *reinterpret_cast<uint32_t*>(Chi + (size_t)row0 * N + col)       = h0;
                *reinterpret_cast<uint32_t*>(Clo + (size_t)row0 * N + col)       = l0;
                *reinterpret_cast<uint32_t*>(Chi + (size_t)(row0 + 8) * N + col) = h1;
                *reinterpret_cast<uint32_t*>(Clo + (size_t)(row0 + 8) * N + col) = l1;
            } else {
                float2 w0, w1;
                w0.x = v00; w0.y = v01; w1.x = v10; w1.y = v11;
                *reinterpret_cast<float2*>(C + (size_t)row0 * N + col)       = w0;
                *reinterpret_cast<float2*>(C + (size_t)(row0 + 8) * N + col) = w1;
            }
        }
    }
}

// ---------------------------------------------------------------------------
// fp32 -> bf16 hi/lo split (elementwise, vectorized x4)
// ---------------------------------------------------------------------------
__global__ void __launch_bounds__(256) split_kernel(
    const float* __restrict__ x, __nv_bfloat16* __restrict__ hi,
    __nv_bfloat16* __restrict__ lo, int n4)
{
    int i = blockIdx.x * 256 + threadIdx.x;
    if (i >= n4) return;
    float4 v = reinterpret_cast<const float4*>(x)[i];
    uint32_t h0, l0, h1, l1;
    bf16_split_pack(v.x, v.y, h0, l0);
    bf16_split_pack(v.z, v.w, h1, l1);
    reinterpret_cast<uint32_t*>(hi)[i * 2 + 0] = h0;
    reinterpret_cast<uint32_t*>(hi)[i * 2 + 1] = h1;
    reinterpret_cast<uint32_t*>(lo)[i * 2 + 0] = l0;
    reinterpret_cast<uint32_t*>(lo)[i * 2 + 1] = l1;
}

// W[K,N] -> Wt_hi/lo[N][K]  (transpose + split)
__global__ void __launch_bounds__(256) split_transpose_kernel(
    const float* __restrict__ W, __nv_bfloat16* __restrict__ Th,
    __nv_bfloat16* __restrict__ Tl, int K, int N)
{
    __shared__ float t[32][33];
    const int n0 = blockIdx.x * 32, k0 = blockIdx.y * 32;
    const int tx = threadIdx.x, ty = threadIdx.y;  // 32 x 8
    #pragma unroll
    for (int i = ty; i < 32; i += 8)
        t[i][tx] = W[(size_t)(k0 + i) * N + n0 + tx];
    __syncthreads();
    #pragma unroll
    for (int i = ty; i < 32; i += 8) {
        float x = t[tx][i];
        __nv_bfloat16 h = __float2bfloat16_rn(x);
        float hf = __bfloat162float(h);
        Th[(size_t)(n0 + i) * K + k0 + tx] = h;
        Tl[(size_t)(n0 + i) * K + k0 + tx] = __float2bfloat16_rn(x - hf);
    }
}

// ---------------------------------------------------------------------------
// Flash attention on mma.sync (bf16 hi/lo, 3-term):
//   S = Qh Kh^T + Qh Kl^T + Ql Kh^T ;  O = Ph Vh + Ph Vl + Pl Vh
// CTA: 128 queries x one (b,h). 8 warps, each owns 16 q rows (softmax local).
// KV tiles of 64, double-buffered cp.async. Output: bf16 hi/lo context.
// ---------------------------------------------------------------------------
#define AT_PAD     72
#define AT_Q_B     (128 * AT_PAD * 2)   // 18432 per Q tile (hi or lo)
#define AT_KV_T    (64 * AT_PAD * 2)    // 9216 per KV tile
#define AT_STAGE   (4 * AT_KV_T)        // 36864 (Kh,Kl,Vh,Vl)
#define AT_SMEM    (2 * AT_Q_B + 2 * AT_STAGE)  // 110592

__device__ __forceinline__ void at_load_kv(
    uint32_t stage, const __nv_bfloat16* __restrict__ Kh,
    const __nv_bfloat16* __restrict__ Kl, const __nv_bfloat16* __restrict__ Vh,
    const __nv_bfloat16* __restrict__ Vl,
    int b, int colbase, int kv0, int tid)
{
    const __nv_bfloat16* srcs[4] = {Kh, Kl, Vh, Vl};
    #pragma unroll
    for (int i = 0; i < 8; i++) {
        int cid  = i * 256 + tid;       // 0..2047
        int tile = cid >> 9;            // 0..3
        int c    = cid & 511;
        int row  = c >> 3;              // 0..63
        int ch   = c & 7;               // 16B chunk
        uint32_t dst = stage + tile * AT_KV_T + (uint32_t)(row * AT_PAD + ch * 8) * 2;
        const __nv_bfloat16* src = srcs[tile]
            + ((size_t)b * LKV_ + kv0 + row) * DMODEL + colbase + ch * 8;
        CP_ASYNC16(dst, src);
    }
}

__global__ void __launch_bounds__(256) attn_mma_kernel(
    const __nv_bfloat16* __restrict__ Qh_g, const __nv_bfloat16* __restrict__ Ql_g,
    const __nv_bfloat16* __restrict__ Kh_g, const __nv_bfloat16* __restrict__ Kl_g,
    const __nv_bfloat16* __restrict__ Vh_g, const __nv_bfloat16* __restrict__ Vl_g,
    __nv_bfloat16* __restrict__ Oh_g, __nv_bfloat16* __restrict__ Ol_g)
{
    extern __shared__ char smem[];
    const uint32_t sb  = smem_u32(smem);
    const uint32_t sQh = sb, sQl = sb + AT_Q_B;
    const uint32_t sKV = sb + 2 * AT_Q_B;

    const int qt = blockIdx.x, h = blockIdx.y, b = blockIdx.z;
    const int tid = threadIdx.x, lane = tid & 31, warp = tid >> 5;
    const int colbase = h * DK;
    const size_t qrow0 = (size_t)b * LQ_ + (size_t)qt * 128;

    // load Q hi/lo tiles (128 rows x 64 bf16)
    #pragma unroll
    for (int i = 0; i < 8; i++) {
        int cid = i * 256 + tid;        // 0..2047
        int t   = cid >> 10;            // 0: hi, 1: lo
        int c   = cid & 1023;
        int row = c >> 3;
        int ch  = c & 7;
        uint32_t dst = (t ? sQl : sQh) + (uint32_t)(row * AT_PAD + ch * 8) * 2;
        const __nv_bfloat16* src = (t ? Ql_g : Qh_g)
            + (qrow0 + row) * DMODEL + colbase + ch * 8;
        CP_ASYNC16(dst, src);
    }
    CP_COMMIT();

    at_load_kv(sKV, Kh_g, Kl_g, Vh_g, Vl_g, b, colbase, 0, tid);
    CP_COMMIT();

    const int a_r = lane & 15;
    const int a_c = (lane >> 4) * 8;
    const int b_r = lane & 7;
    const int b_c = ((lane >> 3) & 1) * 8;
    const int t_r = lane & 15;
    const float scale = 0.125f;

    float oacc[8][4];
    #pragma unroll
    for (int ng = 0; ng < 8; ng++)
        #pragma unroll
        for (int j = 0; j < 4; j++) oacc[ng][j] = 0.f;
    float m0 = -1e30f, m1 = -1e30f, l0 = 0.f, l1 = 0.f;

    const int NT = LKV_ / 64;           // 16
    for (int t = 0; t < NT; t++) {
        if (t + 1 < NT) {
            at_load_kv(sKV + ((t + 1) & 1) * AT_STAGE, Kh_g, Kl_g, Vh_g, Vl_g,
                       b, colbase, (t + 1) * 64, tid);
            CP_COMMIT();
            CP_WAIT(1);
        } else {
            CP_WAIT(0);
        }
        __syncthreads();

        const uint32_t st  = sKV + (t & 1) * AT_STAGE;
        const uint32_t tKh = st + 0 * AT_KV_T;
        const uint32_t tKl = st + 1 * AT_KV_T;
        const uint32_t tVh = st + 2 * AT_KV_T;
        const uint32_t tVl = st + 3 * AT_KV_T;

        // ---- S = Q K^T (3-term) ----
        float sacc[8][4];
        #pragma unroll
        for (int ng = 0; ng < 8; ng++)
            #pragma unroll
            for (int j = 0; j < 4; j++) sacc[ng][j] = 0.f;

        #pragma unroll
        for (int kk = 0; kk < 4; kk++) {
            uint32_t qh4[4], ql4[4];
            uint32_t qoff = (uint32_t)((warp * 16 + a_r) * AT_PAD + kk * 16 + a_c) * 2;
            ldsm_x4(qh4, sQh + qoff);
            ldsm_x4(ql4, sQl + qoff);
            #pragma unroll
            for (int ng = 0; ng < 8; ng++) {
                uint32_t kh2[2], kl2[2];
                uint32_t koff = (uint32_t)((ng * 8 + b_r) * AT_PAD + kk * 16 + b_c) * 2;
                ldsm_x2(kh2, tKh + koff);
                ldsm_x2(kl2, tKl + koff);
                mma_bf16(sacc[ng], qh4, kh2);
                mma_bf16(sacc[ng], qh4, kl2);
                mma_bf16(sacc[ng], ql4, kh2);
            }
        }

        // ---- online softmax (warp-local; lane owns rows r0 = lane>>2, r0+8) ----
        float mx0 = -1e30f, mx1 = -1e30f;
        #pragma unroll
        for (int ng = 0; ng < 8; ng++) {
            sacc[ng][0] *= scale; sacc[ng][1] *= scale;
            sacc[ng][2] *= scale; sacc[ng][3] *= scale;
            mx0 = fmaxf(mx0, fmaxf(sacc[ng][0], sacc[ng][1]));
            mx1 = fmaxf(mx1, fmaxf(sacc[ng][2], sacc[ng][3]));
        }
        mx0 = fmaxf(mx0, __shfl_xor_sync(0xFFFFFFFFu, mx0, 1));
        mx0 = fmaxf(mx0, __shfl_xor_sync(0xFFFFFFFFu, mx0, 2));
        mx1 = fmaxf(mx1, __shfl_xor_sync(0xFFFFFFFFu, mx1, 1));
        mx1 = fmaxf(mx1, __shfl_xor_sync(0xFFFFFFFFu, mx1, 2));

        float mn0 = fmaxf(m0, mx0), mn1 = fmaxf(m1, mx1);
        float corr0 = __expf(m0 - mn0), corr1 = __expf(m1 - mn1);
        float sum0 = 0.f, sum1 = 0.f;
        #pragma unroll
        for (int ng = 0; ng < 8; ng++) {
            float p0 = __expf(sacc[ng][0] - mn0);
            float p1 = __expf(sacc[ng][1] - mn0);
            float p2 = __expf(sacc[ng][2] - mn1);
            float p3 = __expf(sacc[ng][3] - mn1);
            sacc[ng][0] = p0; sacc[ng][1] = p1;
            sacc[ng][2] = p2; sacc[ng][3] = p3;
            sum0 += p0 + p1; sum1 += p2 + p3;
        }
        sum0 += __shfl_xor_sync(0xFFFFFFFFu, sum0, 1);
        sum0 += __shfl_xor_sync(0xFFFFFFFFu, sum0, 2);
        sum1 += __shfl_xor_sync(0xFFFFFFFFu, sum1, 1);
        sum1 += __shfl_xor_sync(0xFFFFFFFFu, sum1, 2);
        l0 = l0 * corr0 + sum0; m0 = mn0;
        l1 = l1 * corr1 + sum1; m1 = mn1;
        #pragma unroll
        for (int ng = 0; ng < 8; ng++) {
            oacc[ng][0] *= corr0; oacc[ng][1] *= corr0;
            oacc[ng][2] *= corr1; oacc[ng][3] *= corr1;
        }

        // ---- P repack: C frags -> A frags (hi/lo) ----
        uint32_t ph[4][4], pl[4][4];
        #pragma unroll
        for (int j = 0; j < 4; j++) {
            bf16_split_pack(sacc[2*j  ][0], sacc[2*j  ][1], ph[j][0], pl[j][0]);
            bf16_split_pack(sacc[2*j  ][2], sacc[2*j  ][3], ph[j][1], pl[j][1]);
            bf16_split_pack(sacc[2*j+1][0], sacc[2*j+1][1], ph[j][2], pl[j][2]);
            bf16_split_pack(sacc[2*j+1][2], sacc[2*j+1][3], ph[j][3], pl[j][3]);
        }

        // ---- O += P V (3-term); V via ldmatrix.trans ----
        #pragma unroll
        for (int j = 0; j < 4; j++) {
            #pragma unroll
            for (int ng = 0; ng < 8; ng++) {
                uint32_t vh2[2], vl2[2];
                uint32_t voff = (uint32_t)((j * 16 + t_r) * AT_PAD + ng * 8) * 2;
                ldsm_x2_trans(vh2, tVh + voff);
                ldsm_x2_trans(vl2, tVl + voff);
                mma_bf16(oacc[ng], ph[j], vh2);
                mma_bf16(oacc[ng], ph[j], vl2);
                mma_bf16(oacc[ng], pl[j], vh2);
            }
        }
        __syncthreads();
    }

    // ---- epilogue: normalize + write bf16 hi/lo context ----
    const float inv0 = 1.f / l0, inv1 = 1.f / l1;
    const int r0 = lane >> 2;
    const size_t row0 = (qrow0 + warp * 16 + r0) * DMODEL;
    const size_t row1 = row0 + 8 * DMODEL;
    #pragma unroll
    for (int ng = 0; ng < 8; ng++) {
        int col = colbase + ng * 8 + (lane & 3) * 2;
        uint32_t h0, lo0, h1, lo1;
        bf16_split_pack(oacc[ng][0] * inv0, oacc[ng][1] * inv0, h0, lo0);
        bf16_split_pack(oacc[ng][2] * inv1, oacc[ng][3] * inv1, h1, lo1);
        *reinterpret_cast<uint32_t*>(Oh_g + row0 + col) = h0;
        *reinterpret_cast<uint32_t*>(Ol_g + row0 + col) = lo0;
        *reinterpret_cast<uint32_t*>(Oh_g + row1 + col) = h1;
        *reinterpret_cast<uint32_t*>(Ol_g + row1 + col) = lo1;
    }
}

// ---------------------------------------------------------------------------
extern "C" void kernel_launch(void* const* d_in, const int* in_sizes, int n_in,
                              void* d_out, int out_size)
{
    const float* q  = (const float*)d_in[0];
    const float* k  = (const float*)d_in[1];
    const float* v  = (const float*)d_in[2];
    const float* Wq = (const float*)d_in[3];
    const float* bq = (const float*)d_in[4];
    const float* Wk = (const float*)d_in[5];
    const float* bk = (const float*)d_in[6];
    const float* Wv = (const float*)d_in[7];
    const float* bv = (const float*)d_in[8];
    const float* Wo = (const float*)d_in[9];
    const float* bo = (const float*)d_in[10];
    float* out = (float*)d_out;

    __nv_bfloat16 *qh, *ql, *kh, *kl, *vh, *vl, *ch, *cl;
    __nv_bfloat16 *Qph, *Qpl, *Kph, *Kpl, *Vph, *Vpl;
    __nv_bfloat16 *Wqh, *Wql, *Wkh, *Wkl, *Wvh, *Wvl, *Woh, *Wol;
    cudaGetSymbolAddress((void**)&qh, g_q_hi);  cudaGetSymbolAddress((void**)&ql, g_q_lo);
    cudaGetSymbolAddress((void**)&kh, g_k_hi);  cudaGetSymbolAddress((void**)&kl, g_k_lo);
    cudaGetSymbolAddress((void**)&vh, g_v_hi);  cudaGetSymbolAddress((void**)&vl, g_v_lo);
    cudaGetSymbolAddress((void**)&ch, g_c_hi);  cudaGetSymbolAddress((void**)&cl, g_c_lo);
    cudaGetSymbolAddress((void**)&Qph, g_Qph);  cudaGetSymbolAddress((void**)&Qpl, g_Qpl);
    cudaGetSymbolAddress((void**)&Kph, g_Kph);  cudaGetSymbolAddress((void**)&Kpl, g_Kpl);
    cudaGetSymbolAddress((void**)&Vph, g_Vph);  cudaGetSymbolAddress((void**)&Vpl, g_Vpl);
    cudaGetSymbolAddress((void**)&Wqh, g_Wqt_hi); cudaGetSymbolAddress((void**)&Wql, g_Wqt_lo);
    cudaGetSymbolAddress((void**)&Wkh, g_Wkt_hi); cudaGetSymbolAddress((void**)&Wkl, g_Wkt_lo);
    cudaGetSymbolAddress((void**)&Wvh, g_Wvt_hi); cudaGetSymbolAddress((void**)&Wvl, g_Wvt_lo);
    cudaGetSymbolAddress((void**)&Woh, g_Wot_hi); cudaGetSymbolAddress((void**)&Wol, g_Wot_lo);

    cudaFuncSetAttribute(gemm_tc_kernel,
                         cudaFuncAttributeMaxDynamicSharedMemorySize, GT_SMEM_TOTAL);
    cudaFuncSetAttribute(attn_mma_kernel,
                         cudaFuncAttributeMaxDynamicSharedMemorySize, AT_SMEM);

    // ---- split inputs + weights to bf16 hi/lo ----
    {
        int n4;
        n4 = MQ * DMODEL / 4;  split_kernel<<<(n4 + 255) / 256, 256>>>(q, qh, ql, n4);
        n4 = MKV * IMGM / 4;   split_kernel<<<(n4 + 255) / 256, 256>>>(k, kh, kl, n4);
        n4 = MKV * IMGM / 4;   split_kernel<<<(n4 + 255) / 256, 256>>>(v, vh, vl, n4);
        dim3 tb(32, 8);
        split_transpose_kernel<<<dim3(DMODEL / 32, DMODEL / 32), tb>>>(Wq, Wqh, Wql, DMODEL, DMODEL);
        split_transpose_kernel<<<dim3(DMODEL / 32, IMGM  / 32), tb>>>(Wk, Wkh, Wkl, IMGM,  DMODEL);
        split_transpose_kernel<<<dim3(DMODEL / 32, IMGM  / 32), tb>>>(Wv, Wvh, Wvl, IMGM,  DMODEL);
        split_transpose_kernel<<<dim3(DMODEL / 32, DMODEL / 32), tb>>>(Wo, Woh, Wol, DMODEL, DMODEL);
    }

    // ---- projections (HMMA, split bf16 hi/lo output) ----
    gemm_tc_kernel<<<dim3(DMODEL / 128, MQ / 128),  256, GT_SMEM_TOTAL>>>(
        qh, ql, Wqh, Wql, bq, nullptr, Qph, Qpl, MQ, DMODEL, DMODEL);
    gemm_tc_kernel<<<dim3(DMODEL / 128, MKV / 128), 256, GT_SMEM_TOTAL>>>(
        kh, kl, Wkh, Wkl, bk, nullptr, Kph, Kpl, MKV, DMODEL, IMGM);
    gemm_tc_kernel<<<dim3(DMODEL / 128, MKV / 128), 256, GT_SMEM_TOTAL>>>(
        vh, vl, Wvh, Wvl, bv, nullptr, Vph, Vpl, MKV, DMODEL, IMGM);

    // ---- fused flash attention (HMMA) -> bf16 hi/lo context ----
    attn_mma_kernel<<<dim3(LQ_ / 128, NHEADS, BATCH), 256, AT_SMEM>>>(
        Qph, Qpl, Kph, Kpl, Vph, Vpl, ch, cl);

    // ---- output projection (fp32 out) ----
    gemm_tc_kernel<<<dim3(DMODEL / 128, MQ / 128), 256, GT_SMEM_TOTAL>>>(
        ch, cl, Woh, Wol, bo, out, nullptr, nullptr, MQ, DMODEL, DMODEL);
}

// round 7
// speedup vs baseline: 2.9960x; 1.0097x over previous
#include <cuda_runtime.h>
#include <cuda_bf16.h>
#include <cstdint>
#include <math.h>

#define DMODEL 1024
#define IMGM   512
#define NHEADS 16
#define DK     64
#define BATCH  8
#define LQ_    2048
#define LKV_   1024
#define MQ   (BATCH * LQ_)    // 16384
#define MKV  (BATCH * LKV_)   // 8192

// ---------------- scratch (static device globals; no allocs allowed) -------
__device__ __nv_bfloat16 g_q_hi[(size_t)MQ  * DMODEL], g_q_lo[(size_t)MQ  * DMODEL];
__device__ __nv_bfloat16 g_k_hi[(size_t)MKV * IMGM ], g_k_lo[(size_t)MKV * IMGM ];
__device__ __nv_bfloat16 g_v_hi[(size_t)MKV * IMGM ], g_v_lo[(size_t)MKV * IMGM ];
__device__ __nv_bfloat16 g_Qph[(size_t)MQ  * DMODEL], g_Qpl[(size_t)MQ  * DMODEL];
__device__ __nv_bfloat16 g_Kph[(size_t)MKV * DMODEL], g_Kpl[(size_t)MKV * DMODEL];
__device__ __nv_bfloat16 g_Vph[(size_t)MKV * DMODEL], g_Vpl[(size_t)MKV * DMODEL];
__device__ __nv_bfloat16 g_c_hi[(size_t)MQ  * DMODEL], g_c_lo[(size_t)MQ  * DMODEL];
__device__ __nv_bfloat16 g_Wqt_hi[DMODEL * DMODEL], g_Wqt_lo[DMODEL * DMODEL];
__device__ __nv_bfloat16 g_Wkt_hi[DMODEL * IMGM ], g_Wkt_lo[DMODEL * IMGM ];
__device__ __nv_bfloat16 g_Wvt_hi[DMODEL * IMGM ], g_Wvt_lo[DMODEL * IMGM ];
__device__ __nv_bfloat16 g_Wot_hi[DMODEL * DMODEL], g_Wot_lo[DMODEL * DMODEL];

// ---------------- PTX helpers ----------------------------------------------
__device__ __forceinline__ uint32_t smem_u32(const void* p) {
    uint32_t a;
    asm("{ .reg .u64 t; cvta.to.shared.u64 t, %1; cvt.u32.u64 %0, t; }"
        : "=r"(a) : "l"(p));
    return a;
}
__device__ __forceinline__ void ldsm_x4(uint32_t* r, uint32_t addr) {
    asm volatile("ldmatrix.sync.aligned.m8n8.x4.shared.b16 {%0,%1,%2,%3}, [%4];"
                 : "=r"(r[0]), "=r"(r[1]), "=r"(r[2]), "=r"(r[3]) : "r"(addr));
}
__device__ __forceinline__ void ldsm_x2(uint32_t* r, uint32_t addr) {
    asm volatile("ldmatrix.sync.aligned.m8n8.x2.shared.b16 {%0,%1}, [%2];"
                 : "=r"(r[0]), "=r"(r[1]) : "r"(addr));
}
__device__ __forceinline__ void ldsm_x2_trans(uint32_t* r, uint32_t addr) {
    asm volatile("ldmatrix.sync.aligned.m8n8.x2.trans.shared.b16 {%0,%1}, [%2];"
                 : "=r"(r[0]), "=r"(r[1]) : "r"(addr));
}
__device__ __forceinline__ void mma_bf16(float* c, const uint32_t* a, const uint32_t* b) {
    asm volatile(
        "mma.sync.aligned.m16n8k16.row.col.f32.bf16.bf16.f32 "
        "{%0,%1,%2,%3}, {%4,%5,%6,%7}, {%8,%9}, {%0,%1,%2,%3};"
        : "+f"(c[0]), "+f"(c[1]), "+f"(c[2]), "+f"(c[3])
        : "r"(a[0]), "r"(a[1]), "r"(a[2]), "r"(a[3]), "r"(b[0]), "r"(b[1]));
}
#define CP_ASYNC16(dst, src) \
    asm volatile("cp.async.cg.shared.global [%0], [%1], 16;" :: "r"(dst), "l"(src) : "memory")
#define CP_COMMIT()  asm volatile("cp.async.commit_group;" ::: "memory")
#define CP_WAIT(n)   asm volatile("cp.async.wait_group %0;" :: "n"(n) : "memory")

__device__ __forceinline__ void bf16_split_pack(float a, float b,
                                                uint32_t& hi, uint32_t& lo) {
    __nv_bfloat16 ha = __float2bfloat16_rn(a), hb = __float2bfloat16_rn(b);
    float ra = a - __bfloat162float(ha);
    float rb = b - __bfloat162float(hb);
    __nv_bfloat162 hp, lp;
    hp.x = ha; hp.y = hb;
    lp.x = __float2bfloat16_rn(ra); lp.y = __float2bfloat16_rn(rb);
    hi = *reinterpret_cast<uint32_t*>(&hp);
    lo = *reinterpret_cast<uint32_t*>(&lp);
}

// ---------------------------------------------------------------------------
// HMMA bf16 GEMM, 3-term hi/lo split. CTA tile 128(M) x 256(N), BK=64.
// 8 warps: 2(M) x 4(N), warp tile 64x64. Double-buffered cp.async.
// Smem rows padded to 72 bf16 (144B) -> conflict-free ldmatrix.
// ---------------------------------------------------------------------------
#define GT_PAD      72
#define GT_ATILE_B  (128 * GT_PAD * 2)   // 18432
#define GT_BTILE_B  (256 * GT_PAD * 2)   // 36864
#define GT_STAGE_B  (2 * GT_ATILE_B + 2 * GT_BTILE_B)   // 110592
#define GT_SMEM_TOTAL (2 * GT_STAGE_B)                  // 221184

__device__ __forceinline__ void gt_load_stage(
    uint32_t stage, const __nv_bfloat16* __restrict__ Ah,
    const __nv_bfloat16* __restrict__ Al, const __nv_bfloat16* __restrict__ Bh,
    const __nv_bfloat16* __restrict__ Bl,
    int bm, int bn, int K, int k0, int tid)
{
    #pragma unroll
    for (int i = 0; i < 24; i++) {
        int cid = i * 256 + tid;        // 0..6143
        int ch  = cid & 7;              // 16B chunk within 64-col row
        uint32_t dst;
        const __nv_bfloat16* src;
        if (cid < 2048) {               // A region: 2 x 1024 chunks
            int row = (cid >> 3) & 127;
            bool hi = cid < 1024;
            src = (hi ? Ah : Al) + (size_t)(bm + row) * K + k0 + ch * 8;
            dst = stage + (hi ? 0u : (uint32_t)GT_ATILE_B)
                + (uint32_t)(row * GT_PAD + ch * 8) * 2;
        } else {                        // B region: 2 x 2048 chunks
            int c2  = cid - 2048;
            int row = (c2 >> 3) & 255;
            bool hi = c2 < 2048;
            src = (hi ? Bh : Bl) + (size_t)(bn + row) * K + k0 + ch * 8;
            dst = stage + 2u * GT_ATILE_B + (hi ? 0u : (uint32_t)GT_BTILE_B)
                + (uint32_t)(row * GT_PAD + ch * 8) * 2;
        }
        CP_ASYNC16(dst, src);
    }
}

__global__ void __launch_bounds__(256, 1) gemm_tc_kernel(
    const __nv_bfloat16* __restrict__ Ah, const __nv_bfloat16* __restrict__ Al,
    const __nv_bfloat16* __restrict__ Bh, const __nv_bfloat16* __restrict__ Bl,
    const float* __restrict__ bias, float* __restrict__ C,
    __nv_bfloat16* __restrict__ Chi, __nv_bfloat16* __restrict__ Clo,
    int M, int N, int K)
{
    extern __shared__ char smem[];
    const uint32_t sb = smem_u32(smem);
    const int tid  = threadIdx.x;
    const int lane = tid & 31;
    const int wid  = tid >> 5;
    const int wm   = wid & 1;            // 0..1 (M)
    const int wn   = wid >> 1;           // 0..3 (N)
    const int bn   = blockIdx.x * 256;
    const int bm   = blockIdx.y * 128;

    float acc[4][8][4];
    #pragma unroll
    for (int mt = 0; mt < 4; mt++)
        #pragma unroll
        for (int nt = 0; nt < 8; nt++)
            #pragma unroll
            for (int j = 0; j < 4; j++) acc[mt][nt][j] = 0.f;

    const int KT = K >> 6;

    gt_load_stage(sb, Ah, Al, Bh, Bl, bm, bn, K, 0, tid);
    CP_COMMIT();

    const int a_r = lane & 15;
    const int a_c = (lane >> 4) * 8;
    // B x4 addressing: covers nt pair (2p, 2p+1)
    const int b_row_l = ((lane >> 4) & 1) * 8 + (lane & 7);
    const int b_col_l = ((lane >> 3) & 1) * 8;

    for (int s = 0; s < KT; s++) {
        if (s + 1 < KT) {
            gt_load_stage(sb + ((s + 1) & 1) * GT_STAGE_B, Ah, Al, Bh, Bl,
                          bm, bn, K, (s + 1) * 64, tid);
            CP_COMMIT();
            CP_WAIT(1);
        } else {
            CP_WAIT(0);
        }
        __syncthreads();

        const uint32_t st  = sb + (s & 1) * GT_STAGE_B;
        const uint32_t sAh = st;
        const uint32_t sAl = st + GT_ATILE_B;
        const uint32_t sBh = st + 2 * GT_ATILE_B;
        const uint32_t sBl = st + 2 * GT_ATILE_B + GT_BTILE_B;

        #pragma unroll
        for (int kk = 0; kk < 4; kk++) {
            uint32_t ah[4][4], al[4][4];
            #pragma unroll
            for (int mt = 0; mt < 4; mt++) {
                uint32_t off = (uint32_t)((wm * 64 + mt * 16 + a_r) * GT_PAD
                                          + kk * 16 + a_c) * 2;
                ldsm_x4(ah[mt], sAh + off);
                ldsm_x4(al[mt], sAl + off);
            }
            #pragma unroll
            for (int p = 0; p < 4; p++) {
                uint32_t bh4[4], bl4[4];
                uint32_t off = (uint32_t)((wn * 64 + p * 16 + b_row_l) * GT_PAD
                                          + kk * 16 + b_col_l) * 2;
                ldsm_x4(bh4, sBh + off);
                ldsm_x4(bl4, sBl + off);
                #pragma unroll
                for (int mt = 0; mt < 4; mt++) {
                    mma_bf16(acc[mt][2*p  ], ah[mt], &bh4[0]);
                    mma_bf16(acc[mt][2*p  ], ah[mt], &bl4[0]);
                    mma_bf16(acc[mt][2*p  ], al[mt], &bh4[0]);
                    mma_bf16(acc[mt][2*p+1], ah[mt], &bh4[2]);
                    mma_bf16(acc[mt][2*p+1], ah[mt], &bl4[2]);
                    mma_bf16(acc[mt][2*p+1], al[mt], &bh4[2]);
                }
            }
        }
        __syncthreads();
    }

    const int er = lane >> 2;
    const int ec = (lane & 3) * 2;
    #pragma unroll
    for (int mt = 0; mt < 4; mt++) {
        #pragma unroll
        for (int nt = 0; nt < 8; nt++) {
            int row0 = bm + wm * 64 + mt * 16 + er;
            int col  = bn + wn * 64 + nt * 8 + ec;
            float b0 = bias[col], b1 = bias[col + 1];
            float v00 = acc[mt][nt][0] + b0, v01 = acc[mt][nt][1] + b1;
            float v10 = acc[mt][nt][2] + b0, v11 = acc[mt][nt][3] + b1;
            if (Chi) {
                uint32_t h0, l0, h1, l1;
                bf16_split_pack(v00, v01, h0, l0);
                bf16_split_pack(v10, v11, h1, l1);
                *reinterpret_cast<uint32_t*>(Chi + (size_t)row0 * N + col)       = h0;
                *reinterpret_cast<uint32_t*>(Clo + (size_t)row0 * N + col)       = l0;
                *reinterpret_cast<uint32_t*>(Chi + (size_t)(row0 + 8) * N + col) = h1;
                *reinterpret_cast<uint32_t*>(Clo + (size_t)(row0 + 8) * N + col) = l1;
            } else {
                float2 w0, w1;
                w0.x = v00; w0.y = v01; w1.x = v10; w1.y = v11;
                *reinterpret_cast<float2*>(C + (size_t)row0 * N + col)       = w0;
                *reinterpret_cast<float2*>(C + (size_t)(row0 + 8) * N + col) = w1;
            }
        }
    }
}

// ---------------------------------------------------------------------------
// fp32 -> bf16 hi/lo split (elementwise, vectorized x4)
// ---------------------------------------------------------------------------
__global__ void __launch_bounds__(256) split_kernel(
    const float* __restrict__ x, __nv_bfloat16* __restrict__ hi,
    __nv_bfloat16* __restrict__ lo, int n4)
{
    int i = blockIdx.x * 256 + threadIdx.x;
    if (i >= n4) return;
    float4 v = reinterpret_cast<const float4*>(x)[i];
    uint32_t h0, l0, h1, l1;
    bf16_split_pack(v.x, v.y, h0, l0);
    bf16_split_pack(v.z, v.w, h1, l1);
    reinterpret_cast<uint32_t*>(hi)[i * 2 + 0] = h0;
    reinterpret_cast<uint32_t*>(hi)[i * 2 + 1] = h1;
    reinterpret_cast<uint32_t*>(lo)[i * 2 + 0] = l0;
    reinterpret_cast<uint32_t*>(lo)[i * 2 + 1] = l1;
}

// W[K,N] -> Wt_hi/lo[N][K]  (transpose + split)
__global__ void __launch_bounds__(256) split_transpose_kernel(
    const float* __restrict__ W, __nv_bfloat16* __restrict__ Th,
    __nv_bfloat16* __restrict__ Tl, int K, int N)
{
    __shared__ float t[32][33];
    const int n0 = blockIdx.x * 32, k0 = blockIdx.y * 32;
    const int tx = threadIdx.x, ty = threadIdx.y;  // 32 x 8
    #pragma unroll
    for (int i = ty; i < 32; i += 8)
        t[i][tx] = W[(size_t)(k0 + i) * N + n0 + tx];
    __syncthreads();
    #pragma unroll
    for (int i = ty; i < 32; i += 8) {
        float x = t[tx][i];
        __nv_bfloat16 h = __float2bfloat16_rn(x);
        float hf = __bfloat162float(h);
        Th[(size_t)(n0 + i) * K + k0 + tx] = h;
        Tl[(size_t)(n0 + i) * K + k0 + tx] = __float2bfloat16_rn(x - hf);
    }
}

// ---------------------------------------------------------------------------
// Flash attention on mma.sync (bf16 hi/lo, 3-term) -- unchanged (round 6)
// ---------------------------------------------------------------------------
#define AT_PAD     72
#define AT_Q_B     (128 * AT_PAD * 2)
#define AT_KV_T    (64 * AT_PAD * 2)
#define AT_STAGE   (4 * AT_KV_T)
#define AT_SMEM    (2 * AT_Q_B + 2 * AT_STAGE)  // 110592

__device__ __forceinline__ void at_load_kv(
    uint32_t stage, const __nv_bfloat16* __restrict__ Kh,
    const __nv_bfloat16* __restrict__ Kl, const __nv_bfloat16* __restrict__ Vh,
    const __nv_bfloat16* __restrict__ Vl,
    int b, int colbase, int kv0, int tid)
{
    const __nv_bfloat16* srcs[4] = {Kh, Kl, Vh, Vl};
    #pragma unroll
    for (int i = 0; i < 8; i++) {
        int cid  = i * 256 + tid;
        int tile = cid >> 9;
        int c    = cid & 511;
        int row  = c >> 3;
        int ch   = c & 7;
        uint32_t dst = stage + tile * AT_KV_T + (uint32_t)(row * AT_PAD + ch * 8) * 2;
        const __nv_bfloat16* src = srcs[tile]
            + ((size_t)b * LKV_ + kv0 + row) * DMODEL + colbase + ch * 8;
        CP_ASYNC16(dst, src);
    }
}

__global__ void __launch_bounds__(256) attn_mma_kernel(
    const __nv_bfloat16* __restrict__ Qh_g, const __nv_bfloat16* __restrict__ Ql_g,
    const __nv_bfloat16* __restrict__ Kh_g, const __nv_bfloat16* __restrict__ Kl_g,
    const __nv_bfloat16* __restrict__ Vh_g, const __nv_bfloat16* __restrict__ Vl_g,
    __nv_bfloat16* __restrict__ Oh_g, __nv_bfloat16* __restrict__ Ol_g)
{
    extern __shared__ char smem[];
    const uint32_t sb  = smem_u32(smem);
    const uint32_t sQh = sb, sQl = sb + AT_Q_B;
    const uint32_t sKV = sb + 2 * AT_Q_B;

    const int qt = blockIdx.x, h = blockIdx.y, b = blockIdx.z;
    const int tid = threadIdx.x, lane = tid & 31, warp = tid >> 5;
    const int colbase = h * DK;
    const size_t qrow0 = (size_t)b * LQ_ + (size_t)qt * 128;

    #pragma unroll
    for (int i = 0; i < 8; i++) {
        int cid = i * 256 + tid;
        int t   = cid >> 10;
        int c   = cid & 1023;
        int row = c >> 3;
        int ch  = c & 7;
        uint32_t dst = (t ? sQl : sQh) + (uint32_t)(row * AT_PAD + ch * 8) * 2;
        const __nv_bfloat16* src = (t ? Ql_g : Qh_g)
            + (qrow0 + row) * DMODEL + colbase + ch * 8;
        CP_ASYNC16(dst, src);
    }
    CP_COMMIT();

    at_load_kv(sKV, Kh_g, Kl_g, Vh_g, Vl_g, b, colbase, 0, tid);
    CP_COMMIT();

    const int a_r = lane & 15;
    const int a_c = (lane >> 4) * 8;
    const int b_r = lane & 7;
    const int b_c = ((lane >> 3) & 1) * 8;
    const int t_r = lane & 15;
    const float scale = 0.125f;

    float oacc[8][4];
    #pragma unroll
    for (int ng = 0; ng < 8; ng++)
        #pragma unroll
        for (int j = 0; j < 4; j++) oacc[ng][j] = 0.f;
    float m0 = -1e30f, m1 = -1e30f, l0 = 0.f, l1 = 0.f;

    const int NT = LKV_ / 64;
    for (int t = 0; t < NT; t++) {
        if (t + 1 < NT) {
            at_load_kv(sKV + ((t + 1) & 1) * AT_STAGE, Kh_g, Kl_g, Vh_g, Vl_g,
                       b, colbase, (t + 1) * 64, tid);
            CP_COMMIT();
            CP_WAIT(1);
        } else {
            CP_WAIT(0);
        }
        __syncthreads();

        const uint32_t st  = sKV + (t & 1) * AT_STAGE;
        const uint32_t tKh = st + 0 * AT_KV_T;
        const uint32_t tKl = st + 1 * AT_KV_T;
        const uint32_t tVh = st + 2 * AT_KV_T;
        const uint32_t tVl = st + 3 * AT_KV_T;

        float sacc[8][4];
        #pragma unroll
        for (int ng = 0; ng < 8; ng++)
            #pragma unroll
            for (int j = 0; j < 4; j++) sacc[ng][j] = 0.f;

        #pragma unroll
        for (int kk = 0; kk < 4; kk++) {
            uint32_t qh4[4], ql4[4];
            uint32_t qoff = (uint32_t)((warp * 16 + a_r) * AT_PAD + kk * 16 + a_c) * 2;
            ldsm_x4(qh4, sQh + qoff);
            ldsm_x4(ql4, sQl + qoff);
            #pragma unroll
            for (int ng = 0; ng < 8; ng++) {
                uint32_t kh2[2], kl2[2];
                uint32_t koff = (uint32_t)((ng * 8 + b_r) * AT_PAD + kk * 16 + b_c) * 2;
                ldsm_x2(kh2, tKh + koff);
                ldsm_x2(kl2, tKl + koff);
                mma_bf16(sacc[ng], qh4, kh2);
                mma_bf16(sacc[ng], qh4, kl2);
                mma_bf16(sacc[ng], ql4, kh2);
            }
        }

        float mx0 = -1e30f, mx1 = -1e30f;
        #pragma unroll
        for (int ng = 0; ng < 8; ng++) {
            sacc[ng][0] *= scale; sacc[ng][1] *= scale;
            sacc[ng][2] *= scale; sacc[ng][3] *= scale;
            mx0 = fmaxf(mx0, fmaxf(sacc[ng][0], sacc[ng][1]));
            mx1 = fmaxf(mx1, fmaxf(sacc[ng][2], sacc[ng][3]));
        }
        mx0 = fmaxf(mx0, __shfl_xor_sync(0xFFFFFFFFu, mx0, 1));
        mx0 = fmaxf(mx0, __shfl_xor_sync(0xFFFFFFFFu, mx0, 2));
        mx1 = fmaxf(mx1, __shfl_xor_sync(0xFFFFFFFFu, mx1, 1));
        mx1 = fmaxf(mx1, __shfl_xor_sync(0xFFFFFFFFu, mx1, 2));

        float mn0 = fmaxf(m0, mx0), mn1 = fmaxf(m1, mx1);
        float corr0 = __expf(m0 - mn0), corr1 = __expf(m1 - mn1);
        float sum0 = 0.f, sum1 = 0.f;
        #pragma unroll
        for (int ng = 0; ng < 8; ng++) {
            float p0 = __expf(sacc[ng][0] - mn0);
            float p1 = __expf(sacc[ng][1] - mn0);
            float p2 = __expf(sacc[ng][2] - mn1);
            float p3 = __expf(sacc[ng][3] - mn1);
            sacc[ng][0] = p0; sacc[ng][1] = p1;
            sacc[ng][2] = p2; sacc[ng][3] = p3;
            sum0 += p0 + p1; sum1 += p2 + p3;
        }
        sum0 += __shfl_xor_sync(0xFFFFFFFFu, sum0, 1);
        sum0 += __shfl_xor_sync(0xFFFFFFFFu, sum0, 2);
        sum1 += __shfl_xor_sync(0xFFFFFFFFu, sum1, 1);
        sum1 += __shfl_xor_sync(0xFFFFFFFFu, sum1, 2);
        l0 = l0 * corr0 + sum0; m0 = mn0;
        l1 = l1 * corr1 + sum1; m1 = mn1;
        #pragma unroll
        for (int ng = 0; ng < 8; ng++) {
            oacc[ng][0] *= corr0; oacc[ng][1] *= corr0;
            oacc[ng][2] *= corr1; oacc[ng][3] *= corr1;
        }

        uint32_t ph[4][4], pl[4][4];
        #pragma unroll
        for (int j = 0; j < 4; j++) {
            bf16_split_pack(sacc[2*j  ][0], sacc[2*j  ][1], ph[j][0], pl[j][0]);
            bf16_split_pack(sacc[2*j  ][2], sacc[2*j  ][3], ph[j][1], pl[j][1]);
            bf16_split_pack(sacc[2*j+1][0], sacc[2*j+1][1], ph[j][2], pl[j][2]);
            bf16_split_pack(sacc[2*j+1][2], sacc[2*j+1][3], ph[j][3], pl[j][3]);
        }

        #pragma unroll
        for (int j = 0; j < 4; j++) {
            #pragma unroll
            for (int ng = 0; ng < 8; ng++) {
                uint32_t vh2[2], vl2[2];
                uint32_t voff = (uint32_t)((j * 16 + t_r) * AT_PAD + ng * 8) * 2;
                ldsm_x2_trans(vh2, tVh + voff);
                ldsm_x2_trans(vl2, tVl + voff);
                mma_bf16(oacc[ng], ph[j], vh2);
                mma_bf16(oacc[ng], ph[j], vl2);
                mma_bf16(oacc[ng], pl[j], vh2);
            }
        }
        __syncthreads();
    }

    const float inv0 = 1.f / l0, inv1 = 1.f / l1;
    const int r0 = lane >> 2;
    const size_t row0 = (qrow0 + warp * 16 + r0) * DMODEL;
    const size_t row1 = row0 + 8 * DMODEL;
    #pragma unroll
    for (int ng = 0; ng < 8; ng++) {
        int col = colbase + ng * 8 + (lane & 3) * 2;
        uint32_t h0, lo0, h1, lo1;
        bf16_split_pack(oacc[ng][0] * inv0, oacc[ng][1] * inv0, h0, lo0);
        bf16_split_pack(oacc[ng][2] * inv1, oacc[ng][3] * inv1, h1, lo1);
        *reinterpret_cast<uint32_t*>(Oh_g + row0 + col) = h0;
        *reinterpret_cast<uint32_t*>(Ol_g + row0 + col) = lo0;
        *reinterpret_cast<uint32_t*>(Oh_g + row1 + col) = h1;
        *reinterpret_cast<uint32_t*>(Ol_g + row1 + col) = lo1;
    }
}

// ---------------------------------------------------------------------------
extern "C" void kernel_launch(void* const* d_in, const int* in_sizes, int n_in,
                              void* d_out, int out_size)
{
    const float* q  = (const float*)d_in[0];
    const float* k  = (const float*)d_in[1];
    const float* v  = (const float*)d_in[2];
    const float* Wq = (const float*)d_in[3];
    const float* bq = (const float*)d_in[4];
    const float* Wk = (const float*)d_in[5];
    const float* bk = (const float*)d_in[6];
    const float* Wv = (const float*)d_in[7];
    const float* bv = (const float*)d_in[8];
    const float* Wo = (const float*)d_in[9];
    const float* bo = (const float*)d_in[10];
    float* out = (float*)d_out;

    __nv_bfloat16 *qh, *ql, *kh, *kl, *vh, *vl, *ch, *cl;
    __nv_bfloat16 *Qph, *Qpl, *Kph, *Kpl, *Vph, *Vpl;
    __nv_bfloat16 *Wqh, *Wql, *Wkh, *Wkl, *Wvh, *Wvl, *Woh, *Wol;
    cudaGetSymbolAddress((void**)&qh, g_q_hi);  cudaGetSymbolAddress((void**)&ql, g_q_lo);
    cudaGetSymbolAddress((void**)&kh, g_k_hi);  cudaGetSymbolAddress((void**)&kl, g_k_lo);
    cudaGetSymbolAddress((void**)&vh, g_v_hi);  cudaGetSymbolAddress((void**)&vl, g_v_lo);
    cudaGetSymbolAddress((void**)&ch, g_c_hi);  cudaGetSymbolAddress((void**)&cl, g_c_lo);
    cudaGetSymbolAddress((void**)&Qph, g_Qph);  cudaGetSymbolAddress((void**)&Qpl, g_Qpl);
    cudaGetSymbolAddress((void**)&Kph, g_Kph);  cudaGetSymbolAddress((void**)&Kpl, g_Kpl);
    cudaGetSymbolAddress((void**)&Vph, g_Vph);  cudaGetSymbolAddress((void**)&Vpl, g_Vpl);
    cudaGetSymbolAddress((void**)&Wqh, g_Wqt_hi); cudaGetSymbolAddress((void**)&Wql, g_Wqt_lo);
    cudaGetSymbolAddress((void**)&Wkh, g_Wkt_hi); cudaGetSymbolAddress((void**)&Wkl, g_Wkt_lo);
    cudaGetSymbolAddress((void**)&Wvh, g_Wvt_hi); cudaGetSymbolAddress((void**)&Wvl, g_Wvt_lo);
    cudaGetSymbolAddress((void**)&Woh, g_Wot_hi); cudaGetSymbolAddress((void**)&Wol, g_Wot_lo);

    cudaFuncSetAttribute(gemm_tc_kernel,
                         cudaFuncAttributeMaxDynamicSharedMemorySize, GT_SMEM_TOTAL);
    cudaFuncSetAttribute(attn_mma_kernel,
                         cudaFuncAttributeMaxDynamicSharedMemorySize, AT_SMEM);

    // ---- split inputs + weights to bf16 hi/lo ----
    {
        int n4;
        n4 = MQ * DMODEL / 4;  split_kernel<<<(n4 + 255) / 256, 256>>>(q, qh, ql, n4);
        n4 = MKV * IMGM / 4;   split_kernel<<<(n4 + 255) / 256, 256>>>(k, kh, kl, n4);
        n4 = MKV * IMGM / 4;   split_kernel<<<(n4 + 255) / 256, 256>>>(v, vh, vl, n4);
        dim3 tb(32, 8);
        split_transpose_kernel<<<dim3(DMODEL / 32, DMODEL / 32), tb>>>(Wq, Wqh, Wql, DMODEL, DMODEL);
        split_transpose_kernel<<<dim3(DMODEL / 32, IMGM  / 32), tb>>>(Wk, Wkh, Wkl, IMGM,  DMODEL);
        split_transpose_kernel<<<dim3(DMODEL / 32, IMGM  / 32), tb>>>(Wv, Wvh, Wvl, IMGM,  DMODEL);
        split_transpose_kernel<<<dim3(DMODEL / 32, DMODEL / 32), tb>>>(Wo, Woh, Wol, DMODEL, DMODEL);
    }

    // ---- projections (HMMA, split bf16 hi/lo output) ----
    gemm_tc_kernel<<<dim3(DMODEL / 256, MQ / 128),  256, GT_SMEM_TOTAL>>>(
        qh, ql, Wqh, Wql, bq, nullptr, Qph, Qpl, MQ, DMODEL, DMODEL);
    gemm_tc_kernel<<<dim3(DMODEL / 256, MKV / 128), 256, GT_SMEM_TOTAL>>>(
        kh, kl, Wkh, Wkl, bk, nullptr, Kph, Kpl, MKV, DMODEL, IMGM);
    gemm_tc_kernel<<<dim3(DMODEL / 256, MKV / 128), 256, GT_SMEM_TOTAL>>>(
        vh, vl, Wvh, Wvl, bv, nullptr, Vph, Vpl, MKV, DMODEL, IMGM);

    // ---- fused flash attention (HMMA) -> bf16 hi/lo context ----
    attn_mma_kernel<<<dim3(LQ_ / 128, NHEADS, BATCH), 256, AT_SMEM>>>(
        Qph, Qpl, Kph, Kpl, Vph, Vpl, ch, cl);

    // ---- output projection (fp32 out) ----
    gemm_tc_kernel<<<dim3(DMODEL / 256, MQ / 128), 256, GT_SMEM_TOTAL>>>(
        ch, cl, Woh, Wol, bo, out, nullptr, nullptr, MQ, DMODEL, DMODEL);
}